// round 14
// baseline (speedup 1.0000x reference)
#include <cuda_runtime.h>
#include <cuda_bf16.h>
#include <cuda_fp16.h>
#include <math.h>

// BboxSemanticAtt: out[b,y,x] = sigmoid( sum_i c_i * [y1<=y<y2][x1<=x<x2] )
// preds: [B, 256, 5] f32; out: [B, 512, 512] f32.
//
// R10 structure (best measured): dense transposed stores (lane l owns quads
// [128g+4l,128g+4l+4); each STG.128 = contiguous 512B warp burst), one build
// per 32-row block (warp 0 scatters + scans anchor row), warps 1-3 catch up
// via bucketed events (broadcast LDS). NEW: sigmoid via tanh.approx.f16x2 —
// one MUFU per TWO elements (halves the dominant MIO/MUFU stream); HFMA2 for
// 0.5*t+0.5; f32 unpack for stores. v holds g/2 (conf pre-halved).

#define FEAT   512
#define NBOX   256
#define NWARPS 4
#define CHUNK  8
#define NTHREADS 128
#define ROWS_PER_BLOCK 32                  // 4 warps x 8 rows
#define ROW_WORDS 516                      // 512 + slot for x2=512 (+ pad)
#define EVCAP  8

__global__ __launch_bounds__(NTHREADS, 12)
void bbox_att_kernel(const float* __restrict__ preds,
                     float* __restrict__ out,
                     int blocksPerBatch)
{
    __shared__ uint2 sbox[NBOX];                     // {x1|x2<<16, y1|y2<<16}
    __shared__ float sc  [NBOX];                     // 0.5 * conf
    __shared__ float brow[ROW_WORDS];                // build row -> scanned row
    __shared__ uint2 ev  [ROWS_PER_BLOCK][EVCAP];    // per-row event buckets
    __shared__ int   evn [ROWS_PER_BLOCK];
    __shared__ unsigned rowMaskS, ovMaskS;

    const int b       = blockIdx.x / blocksPerBatch;
    const int rowBase = (blockIdx.x % blocksPerBatch) * ROWS_PER_BLOCK;
    const int tid     = threadIdx.x;
    const int warp    = tid >> 5;
    const int lane    = tid & 31;

    if (tid < ROWS_PER_BLOCK) evn[tid] = 0;
    if (tid == 0) { rowMaskS = 0u; ovMaskS = 0u; }
    __syncthreads();

    // ---- load + quantize boxes; bucket ALL in-block enter/exit events ----
    for (int i = tid; i < NBOX; i += NTHREADS) {
        const float* p = preds + ((size_t)b * NBOX + i) * 5;
        float c  = p[0];
        int x1 = min(max((int)floorf(p[1] * 512.0f), 0), FEAT);
        int y1 = min(max((int)floorf(p[2] * 512.0f), 0), FEAT);
        int x2 = min(max((int)floorf(p[3] * 512.0f), 0), FEAT);
        int y2 = min(max((int)floorf(p[4] * 512.0f), 0), FEAT);
        if (!((x2 > x1) && (y2 > y1))) { y1 = 0; y2 = 0; }   // empty y-range
        sbox[i] = make_uint2((unsigned)(x1 | (x2 << 16)),
                             (unsigned)(y1 | (y2 << 16)));
        float hc = 0.5f * c;                                  // pre-halved
        sc[i] = hc;

        unsigned xp = (unsigned)x1 | ((unsigned)x2 << 10);
        int d1 = y1 - rowBase;                                // enter
        if (d1 > 0 && d1 < ROWS_PER_BLOCK) {
            atomicOr(&rowMaskS, 1u << d1);
            int e = atomicAdd(&evn[d1], 1);
            if (e < EVCAP) ev[d1][e] = make_uint2(xp, __float_as_uint(hc));
            else           atomicOr(&ovMaskS, 1u << d1);
        }
        int d2 = y2 - rowBase;                                // exit
        if (d2 > 0 && d2 < ROWS_PER_BLOCK) {
            atomicOr(&rowMaskS, 1u << d2);
            int e = atomicAdd(&evn[d2], 1);
            if (e < EVCAP) ev[d2][e] = make_uint2(xp, __float_as_uint(-hc));
            else           atomicOr(&ovMaskS, 1u << d2);
        }
    }
    __syncthreads();
    const unsigned rowMask = rowMaskS;
    const unsigned ovMask  = ovMaskS;

    // v[4g+j] = half-sum for column (128g + 4*lane + j)
    float v[16];
    float4* brow4 = (float4*)brow;

    // ---- warp 0: build + scan the block anchor row (rowBase) ----
    if (warp == 0) {
        #pragma unroll
        for (int i = lane; i < ROW_WORDS / 4; i += 32)
            brow4[i] = make_float4(0.f, 0.f, 0.f, 0.f);
        __syncwarp();

        #pragma unroll
        for (int i = lane; i < NBOX; i += 32) {
            uint2 bx = sbox[i];
            int y1 = (int)(bx.y & 0xFFFF), y2 = (int)(bx.y >> 16);
            if (y1 <= rowBase && rowBase < y2) {
                float hc = sc[i];
                atomicAdd(&brow[(int)(bx.x & 0xFFFF)],  hc);
                atomicAdd(&brow[(int)(bx.x >> 16)],    -hc);
            }
        }
        __syncwarp();

        // quad-local scans + per-g warp scans + cross-g offsets
        float4 f[4];
        #pragma unroll
        for (int g = 0; g < 4; g++) f[g] = brow4[g * 32 + lane];
        const float* fs = (const float*)f;
        float incl[4];
        #pragma unroll
        for (int g = 0; g < 4; g++) {
            float run = 0.0f;
            #pragma unroll
            for (int j = 0; j < 4; j++) { run += fs[g * 4 + j]; v[g * 4 + j] = run; }
            incl[g] = run;
        }
        #pragma unroll
        for (int o = 1; o < 32; o <<= 1) {
            float t0 = __shfl_up_sync(0xFFFFFFFFu, incl[0], o);
            float t1 = __shfl_up_sync(0xFFFFFFFFu, incl[1], o);
            float t2 = __shfl_up_sync(0xFFFFFFFFu, incl[2], o);
            float t3 = __shfl_up_sync(0xFFFFFFFFu, incl[3], o);
            if (lane >= o) { incl[0] += t0; incl[1] += t1; incl[2] += t2; incl[3] += t3; }
        }
        float off = 0.0f;
        #pragma unroll
        for (int g = 0; g < 4; g++) {
            float e = __shfl_up_sync(0xFFFFFFFFu, incl[g], 1);
            if (lane == 0) e = 0.0f;
            float add = off + e;
            #pragma unroll
            for (int j = 0; j < 4; j++) v[g * 4 + j] += add;
            off += __shfl_sync(0xFFFFFFFFu, incl[g], 31);     // total of group g
        }

        // write scanned row back (dense STS.128, same layout)
        #pragma unroll
        for (int g = 0; g < 4; g++) brow4[g * 32 + lane] = ((float4*)v)[g];
    }
    __syncthreads();

    // ---- warps 1-3: load scanned row, catch up to own anchor via events ----
    if (warp != 0) {
        #pragma unroll
        for (int g = 0; g < 4; g++) ((float4*)v)[g] = brow4[g * 32 + lane];

        const int upto = warp * CHUNK;                 // apply offsets [1, upto]
        unsigned m = rowMask & ((2u << upto) - 2u);    // bits 1..upto
        while (m) {
            int t = __ffs(m) - 1; m &= m - 1;
            if (!((ovMask >> t) & 1u)) {
                const int n = evn[t];
                for (int k = 0; k < n; k++) {
                    uint2 e = ev[t][k];
                    int x1 = (int)(e.x & 0x3FF);
                    int x2 = (int)((e.x >> 10) & 0x3FF);
                    float c2 = __uint_as_float(e.y);
                    #pragma unroll
                    for (int g = 0; g < 4; g++) {
                        int base = g * 128 + 4 * lane;
                        int l0 = max(x1 - base, 0), h0 = min(x2 - base, 4);
                        if (l0 < h0) {
                            #pragma unroll
                            for (int j = 0; j < 4; j++)
                                if (j >= l0 && j < h0) v[g * 4 + j] += c2;
                        }
                    }
                }
            } else {                                   // rare overflow: rescan
                const int yt = rowBase + t;
                for (int i = 0; i < NBOX; i++) {
                    uint2 bx = sbox[i];
                    int y1 = (int)(bx.y & 0xFFFF), y2 = (int)(bx.y >> 16);
                    bool en = (y1 == yt), ex = (y2 == yt && y2 > y1);
                    if (en || ex) {
                        float c2 = en ? sc[i] : -sc[i];
                        int x1 = (int)(bx.x & 0xFFFF);
                        int x2 = (int)(bx.x >> 16);
                        #pragma unroll
                        for (int g = 0; g < 4; g++) {
                            int base = g * 128 + 4 * lane;
                            int l0 = max(x1 - base, 0), h0 = min(x2 - base, 4);
                            if (l0 < h0) {
                                #pragma unroll
                                for (int j = 0; j < 4; j++)
                                    if (j >= l0 && j < h0) v[g * 4 + j] += c2;
                            }
                        }
                    }
                }
            }
        }
    }

    // ---- per-row: prefetch events, f16x2 sigmoid + DENSE store, apply ----
    const int y0 = rowBase + warp * CHUNK;
    float4* dstRow = (float4*)(out + (((size_t)b * FEAT + y0) * FEAT));
    const __half2 h05 = __floats2half2_rn(0.5f, 0.5f);

    for (int r = 0; r < CHUNK; r++) {
        // hoist next-row event loads above the MUFU/STG block (hide LDS lat)
        const int target = warp * CHUNK + r + 1;
        bool have = false, ovf = false;
        int n = 0;
        uint2 e0 = make_uint2(0u, 0u);
        if (r + 1 < CHUNK) {
            have = (rowMask >> target) & 1u;
            if (have) {
                ovf = (ovMask >> target) & 1u;
                n   = evn[target];
                e0  = ev[target][0];
            }
        }

        float4* dst = dstRow + (size_t)r * (FEAT / 4);
        #pragma unroll
        for (int g = 0; g < 4; g++) {
            // pack pairs -> f16x2, one MUFU.TANH per two elements
            unsigned p0, p1, t0, t1;
            asm("cvt.rn.f16x2.f32 %0, %1, %2;" : "=r"(p0)
                : "f"(v[g * 4 + 1]), "f"(v[g * 4 + 0]));      // hi=v1, lo=v0
            asm("cvt.rn.f16x2.f32 %0, %1, %2;" : "=r"(p1)
                : "f"(v[g * 4 + 3]), "f"(v[g * 4 + 2]));      // hi=v3, lo=v2
            asm("tanh.approx.f16x2 %0, %1;" : "=r"(t0) : "r"(p0));
            asm("tanh.approx.f16x2 %0, %1;" : "=r"(t1) : "r"(p1));
            __half2 h0 = *reinterpret_cast<__half2*>(&t0);
            __half2 h1 = *reinterpret_cast<__half2*>(&t1);
            h0 = __hfma2(h0, h05, h05);                        // 0.5*t + 0.5
            h1 = __hfma2(h1, h05, h05);
            float2 f0 = __half22float2(h0);
            float2 f1 = __half22float2(h1);
            dst[g * 32 + lane] = make_float4(f0.x, f0.y, f1.x, f1.y);
        }

        if (have) {
            if (!ovf) {
                for (int k = 0; k < n; k++) {
                    uint2 e = (k == 0) ? e0 : ev[target][k];
                    int x1 = (int)(e.x & 0x3FF);
                    int x2 = (int)((e.x >> 10) & 0x3FF);
                    float c2 = __uint_as_float(e.y);
                    #pragma unroll
                    for (int g = 0; g < 4; g++) {
                        int base = g * 128 + 4 * lane;
                        int l0 = max(x1 - base, 0), h0 = min(x2 - base, 4);
                        if (l0 < h0) {
                            #pragma unroll
                            for (int j = 0; j < 4; j++)
                                if (j >= l0 && j < h0) v[g * 4 + j] += c2;
                        }
                    }
                }
            } else {                                   // rare overflow: rescan
                const int yt = y0 + r + 1;
                for (int i = 0; i < NBOX; i++) {
                    uint2 bx = sbox[i];
                    int y1 = (int)(bx.y & 0xFFFF), y2 = (int)(bx.y >> 16);
                    bool en = (y1 == yt), ex = (y2 == yt && y2 > y1);
                    if (en || ex) {
                        float c2 = en ? sc[i] : -sc[i];
                        int x1 = (int)(bx.x & 0xFFFF);
                        int x2 = (int)(bx.x >> 16);
                        #pragma unroll
                        for (int g = 0; g < 4; g++) {
                            int base = g * 128 + 4 * lane;
                            int l0 = max(x1 - base, 0), h0 = min(x2 - base, 4);
                            if (l0 < h0) {
                                #pragma unroll
                                for (int j = 0; j < 4; j++)
                                    if (j >= l0 && j < h0) v[g * 4 + j] += c2;
                            }
                        }
                    }
                }
            }
        }
    }
}

extern "C" void kernel_launch(void* const* d_in, const int* in_sizes, int n_in,
                              void* d_out, int out_size)
{
    const float* preds = (const float*)d_in[0];
    float* out = (float*)d_out;

    int B = in_sizes[0] / (NBOX * 5);               // 64 for bench shapes
    int blocksPerBatch = FEAT / ROWS_PER_BLOCK;     // 16
    dim3 grid(B * blocksPerBatch);                  // 1024
    dim3 block(NTHREADS);
    bbox_att_kernel<<<grid, block>>>(preds, out, blocksPerBatch);
}